// round 6
// baseline (speedup 1.0000x reference)
#include <cuda_runtime.h>

// param_distance: K=8, B=32, N=4096, D=64 ; BN = 131072
// out[row] = agg[argmin_k sum_d |t[row,d]-agg[k,row,d]|, row, 0]
//
// Persistent grid-stride version: 8 blocks resident per SM, each warp loops
// over rows (stride = total warps). Eliminates ~14 wave transitions of the
// flat-grid launch; memory pattern per iteration identical to the R3 winner
// (warp-per-row, float2 per lane, 9 batched streaming loads, split-butterfly
// reduction + argmin butterfly with first-index tie-break).

__global__ __launch_bounds__(256, 8)
void param_distance_kernel(const float* __restrict__ tensor,
                           const float* __restrict__ agg,
                           float* __restrict__ out,
                           int BN)
{
    const int lane       = threadIdx.x & 31;
    const int warp_gid   = blockIdx.x * (blockDim.x >> 5) + (threadIdx.x >> 5);
    const int warp_total = gridDim.x * (blockDim.x >> 5);
    const size_t kstride = (size_t)BN * 64;

    for (int row = warp_gid; row < BN; row += warp_total) {
        const size_t rbase = (size_t)row * 64;

        const float2 tv = __ldcs(reinterpret_cast<const float2*>(tensor + rbase + lane * 2));

        float2 av[8];
#pragma unroll
        for (int k = 0; k < 8; ++k)
            av[k] = __ldcs(reinterpret_cast<const float2*>(agg + (size_t)k * kstride + rbase + lane * 2));

        float p[8];
#pragma unroll
        for (int k = 0; k < 8; ++k)
            p[k] = fabsf(tv.x - av[k].x) + fabsf(tv.y - av[k].y);

        // ---- split butterfly: distribute the 8 sums across lane groups ----
        const bool hi16 = (lane & 16) != 0;
        float q[4];
#pragma unroll
        for (int j = 0; j < 4; ++j) {
            float send = hi16 ? p[j] : p[j + 4];
            float recv = __shfl_xor_sync(0xFFFFFFFFu, send, 16);
            q[j] = (hi16 ? p[j + 4] : p[j]) + recv;
        }
        const bool hi8 = (lane & 8) != 0;
        float r[2];
#pragma unroll
        for (int j = 0; j < 2; ++j) {
            float send = hi8 ? q[j] : q[j + 2];
            float recv = __shfl_xor_sync(0xFFFFFFFFu, send, 8);
            r[j] = (hi8 ? q[j + 2] : q[j]) + recv;
        }
        const bool hi4 = (lane & 4) != 0;
        float s;
        {
            float send = hi4 ? r[0] : r[1];
            float recv = __shfl_xor_sync(0xFFFFFFFFu, send, 4);
            s = (hi4 ? r[1] : r[0]) + recv;
        }
        s += __shfl_xor_sync(0xFFFFFFFFu, s, 2);
        s += __shfl_xor_sync(0xFFFFFFFFu, s, 1);

        // lane's candidate index: k bit2 = lane bit4, k bit1 = lane bit3, k bit0 = lane bit2
        const int myk = (lane >> 2) & 7;

        // ---- argmin butterfly over offsets 4,8,16 (replicas consistent) ----
        float bv = s;
        int   bk = myk;
#pragma unroll
        for (int off = 4; off <= 16; off <<= 1) {
            float ov = __shfl_xor_sync(0xFFFFFFFFu, bv, off);
            int   ok = __shfl_xor_sync(0xFFFFFFFFu, bk, off);
            if (ov < bv || (ov == bv && ok < bk)) { bv = ov; bk = ok; }
        }

        if (lane == 0) {
            // feature element 0 of candidate bk lives in lane 0's av[bk].x
            float a0 = av[0].x;
            a0 = (bk == 1) ? av[1].x : a0;
            a0 = (bk == 2) ? av[2].x : a0;
            a0 = (bk == 3) ? av[3].x : a0;
            a0 = (bk == 4) ? av[4].x : a0;
            a0 = (bk == 5) ? av[5].x : a0;
            a0 = (bk == 6) ? av[6].x : a0;
            a0 = (bk == 7) ? av[7].x : a0;
            out[row] = a0;
        }
    }
}

extern "C" void kernel_launch(void* const* d_in, const int* in_sizes, int n_in,
                              void* d_out, int out_size)
{
    const float* tensor = (const float*)d_in[0];   // [B, N, D] fp32
    const float* agg    = (const float*)d_in[1];   // [K, B, N, D] fp32
    float* out          = (float*)d_out;           // [1, B, N, 1] fp32

    const int D  = 64;
    const int BN = in_sizes[0] / D;                // 131072

    const int threads = 256;                       // 8 warps per block
    const int blocks  = 152 * 8;                   // persistent: 8 blocks / SM on GB300 (152 SMs)

    param_distance_kernel<<<blocks, threads>>>(tensor, agg, out, BN);
}

// round 7
// speedup vs baseline: 1.0393x; 1.0393x over previous
#include <cuda_runtime.h>

// param_distance: K=8, B=32, N=4096, D=64 ; BN = 131072
// out[row] = agg[argmin_k sum_d |t[row,d]-agg[k,row,d]|, row, 0]
//
// Persistent + software-pipelined: each warp prefetches the NEXT row's 9 loads
// before reducing the current row, so gmem loads are always in flight (no
// loop-carried latency bubble, no wave-transition gaps).
// av[] registers die as soon as p[k] is formed; the winner's feature-0 value
// is re-fetched by lane 0 after argmin (negligible extra traffic, overlapped).

__device__ __forceinline__ void load_row(const float* __restrict__ tensor,
                                         const float* __restrict__ agg,
                                         size_t kstride, int row, int lane,
                                         float2& tv, float2 (&av)[8])
{
    const size_t rbase = (size_t)row * 64 + (size_t)lane * 2;
    tv = __ldcs(reinterpret_cast<const float2*>(tensor + rbase));
#pragma unroll
    for (int k = 0; k < 8; ++k)
        av[k] = __ldcs(reinterpret_cast<const float2*>(agg + (size_t)k * kstride + rbase));
}

__device__ __forceinline__ void diffs(const float2& tv, const float2 (&av)[8],
                                      float (&p)[8])
{
#pragma unroll
    for (int k = 0; k < 8; ++k)
        p[k] = fabsf(tv.x - av[k].x) + fabsf(tv.y - av[k].y);
}

// split butterfly (9 SHFL) + argmin butterfly (6 SHFL); returns winning k
// (first-index tie-break), uniform across the warp.
__device__ __forceinline__ int reduce_argmin(float (&p)[8], int lane)
{
    const bool hi16 = (lane & 16) != 0;
    float q[4];
#pragma unroll
    for (int j = 0; j < 4; ++j) {
        float send = hi16 ? p[j] : p[j + 4];
        float recv = __shfl_xor_sync(0xFFFFFFFFu, send, 16);
        q[j] = (hi16 ? p[j + 4] : p[j]) + recv;
    }
    const bool hi8 = (lane & 8) != 0;
    float r[2];
#pragma unroll
    for (int j = 0; j < 2; ++j) {
        float send = hi8 ? q[j] : q[j + 2];
        float recv = __shfl_xor_sync(0xFFFFFFFFu, send, 8);
        r[j] = (hi8 ? q[j + 2] : q[j]) + recv;
    }
    const bool hi4 = (lane & 4) != 0;
    float s;
    {
        float send = hi4 ? r[0] : r[1];
        float recv = __shfl_xor_sync(0xFFFFFFFFu, send, 4);
        s = (hi4 ? r[1] : r[0]) + recv;
    }
    s += __shfl_xor_sync(0xFFFFFFFFu, s, 2);
    s += __shfl_xor_sync(0xFFFFFFFFu, s, 1);

    float bv = s;
    int   bk = (lane >> 2) & 7;   // k bit2=lane bit4, bit1=lane bit3, bit0=lane bit2
#pragma unroll
    for (int off = 4; off <= 16; off <<= 1) {
        float ov = __shfl_xor_sync(0xFFFFFFFFu, bv, off);
        int   ok = __shfl_xor_sync(0xFFFFFFFFu, bk, off);
        if (ov < bv || (ov == bv && ok < bk)) { bv = ov; bk = ok; }
    }
    return bk;   // uniform across warp
}

__global__ __launch_bounds__(256, 4)
void param_distance_kernel(const float* __restrict__ tensor,
                           const float* __restrict__ agg,
                           float* __restrict__ out,
                           int BN)
{
    const int lane       = threadIdx.x & 31;
    const int warp_gid   = blockIdx.x * (blockDim.x >> 5) + (threadIdx.x >> 5);
    const int warp_total = gridDim.x * (blockDim.x >> 5);
    const size_t kstride = (size_t)BN * 64;

    int row = warp_gid;
    if (row >= BN) return;

    // prologue: load + diff row 0 (av registers die here)
    float p[8];
    {
        float2 tv, av[8];
        load_row(tensor, agg, kstride, row, lane, tv, av);
        diffs(tv, av, p);
    }

    while (true) {
        const int next = row + warp_total;
        const bool have_next = next < BN;

        // prefetch next row BEFORE reducing current row
        float2 tvn, avn[8];
        if (have_next)
            load_row(tensor, agg, kstride, next, lane, tvn, avn);

        // reduce current row (shuffle latency overlaps prefetch)
        const int bk = reduce_argmin(p, lane);

        if (lane == 0) {
            // re-fetch the winner's feature element 0 (tiny, overlapped)
            const float a0 = __ldg(agg + (size_t)bk * kstride + (size_t)row * 64);
            out[row] = a0;
        }

        if (!have_next) break;
        diffs(tvn, avn, p);   // waits for prefetched data; avn dies here
        row = next;
    }
}

extern "C" void kernel_launch(void* const* d_in, const int* in_sizes, int n_in,
                              void* d_out, int out_size)
{
    const float* tensor = (const float*)d_in[0];   // [B, N, D] fp32
    const float* agg    = (const float*)d_in[1];   // [K, B, N, D] fp32
    float* out          = (float*)d_out;           // [1, B, N, 1] fp32

    const int D  = 64;
    const int BN = in_sizes[0] / D;                // 131072

    const int threads = 256;                       // 8 warps per block
    const int blocks  = 152 * 4;                   // persistent: 4 blocks/SM @ <=64 regs

    param_distance_kernel<<<blocks, threads>>>(tensor, agg, out, BN);
}

// round 8
// speedup vs baseline: 1.0764x; 1.0358x over previous
#include <cuda_runtime.h>

// param_distance: K=8, B=32, N=4096, D=64 ; BN = 131072
// out[row] = agg[argmin_k sum_d |t[row,d]-agg[k,row,d]|, row, 0]
//
// R3 winner structure (warp-per-row, float2 per lane, 9 batched streaming
// loads, split-butterfly + argmin-butterfly), with 512-thread blocks:
// each block covers 16 consecutive rows -> 4KB contiguous per gmem stream,
// improving HBM row-buffer locality. Resident warps/SM unchanged (64).

__global__ __launch_bounds__(512, 4)
void param_distance_kernel(const float* __restrict__ tensor,
                           const float* __restrict__ agg,
                           float* __restrict__ out,
                           int BN)
{
    const int row  = blockIdx.x * (blockDim.x >> 5) + (threadIdx.x >> 5);
    const int lane = threadIdx.x & 31;
    if (row >= BN) return;

    const size_t rbase   = (size_t)row * 64;
    const size_t kstride = (size_t)BN * 64;

    const float2 tv = __ldcs(reinterpret_cast<const float2*>(tensor + rbase + lane * 2));

    float2 av[8];
#pragma unroll
    for (int k = 0; k < 8; ++k)
        av[k] = __ldcs(reinterpret_cast<const float2*>(agg + (size_t)k * kstride + rbase + lane * 2));

    float p[8];
#pragma unroll
    for (int k = 0; k < 8; ++k)
        p[k] = fabsf(tv.x - av[k].x) + fabsf(tv.y - av[k].y);

    // ---- split butterfly: distribute the 8 sums across lane groups ----
    const bool hi16 = (lane & 16) != 0;
    float q[4];
#pragma unroll
    for (int j = 0; j < 4; ++j) {
        float send = hi16 ? p[j] : p[j + 4];
        float recv = __shfl_xor_sync(0xFFFFFFFFu, send, 16);
        q[j] = (hi16 ? p[j + 4] : p[j]) + recv;
    }
    const bool hi8 = (lane & 8) != 0;
    float r[2];
#pragma unroll
    for (int j = 0; j < 2; ++j) {
        float send = hi8 ? q[j] : q[j + 2];
        float recv = __shfl_xor_sync(0xFFFFFFFFu, send, 8);
        r[j] = (hi8 ? q[j + 2] : q[j]) + recv;
    }
    const bool hi4 = (lane & 4) != 0;
    float s;
    {
        float send = hi4 ? r[0] : r[1];
        float recv = __shfl_xor_sync(0xFFFFFFFFu, send, 4);
        s = (hi4 ? r[1] : r[0]) + recv;
    }
    s += __shfl_xor_sync(0xFFFFFFFFu, s, 2);
    s += __shfl_xor_sync(0xFFFFFFFFu, s, 1);

    // lane's candidate index: k bit2 = lane bit4, k bit1 = lane bit3, k bit0 = lane bit2
    const int myk = (lane >> 2) & 7;

    // ---- argmin butterfly over offsets 4,8,16 (replicas consistent) ----
    float bv = s;
    int   bk = myk;
#pragma unroll
    for (int off = 4; off <= 16; off <<= 1) {
        float ov = __shfl_xor_sync(0xFFFFFFFFu, bv, off);
        int   ok = __shfl_xor_sync(0xFFFFFFFFu, bk, off);
        if (ov < bv || (ov == bv && ok < bk)) { bv = ov; bk = ok; }
    }
    // all lanes now agree on bk (first-index tie-break preserved)

    if (lane == 0) {
        // feature element 0 of candidate bk lives in lane 0's av[bk].x
        float a0 = av[0].x;
        a0 = (bk == 1) ? av[1].x : a0;
        a0 = (bk == 2) ? av[2].x : a0;
        a0 = (bk == 3) ? av[3].x : a0;
        a0 = (bk == 4) ? av[4].x : a0;
        a0 = (bk == 5) ? av[5].x : a0;
        a0 = (bk == 6) ? av[6].x : a0;
        a0 = (bk == 7) ? av[7].x : a0;
        out[row] = a0;
    }
}

extern "C" void kernel_launch(void* const* d_in, const int* in_sizes, int n_in,
                              void* d_out, int out_size)
{
    const float* tensor = (const float*)d_in[0];   // [B, N, D] fp32
    const float* agg    = (const float*)d_in[1];   // [K, B, N, D] fp32
    float* out          = (float*)d_out;           // [1, B, N, 1] fp32

    const int D  = 64;
    const int BN = in_sizes[0] / D;                // 131072

    const int threads = 512;                       // 16 warps -> 16 rows per block
    const int rows_per_block = threads / 32;
    const int blocks = (BN + rows_per_block - 1) / rows_per_block;

    param_distance_kernel<<<blocks, threads>>>(tensor, agg, out, BN);
}